// round 5
// baseline (speedup 1.0000x reference)
#include <cuda_runtime.h>
#include <math.h>

#define HX_B 16
#define HX_C 256
#define HX_H 128
#define HX_W 128
#define HX_HW (HX_H * HX_W)      // 16384
#define HX_HW4 (HX_HW / 4)       // 4096

#define CH_B 2                   // batches per chunk (32 MiB of x)
#define NCHUNK (HX_B / CH_B)     // 8 chunks

#define RED_SLICES 16            // C split 16 ways in reduce
#define RED_CPT (HX_C / RED_SLICES)  // 16 channels per thread
#define RED_PIX 16               // float4 pixels per reduce block
#define NRED_BLOCKS (CH_B * HX_HW4 / RED_PIX)   // 512

#define APP_SLICES 16            // C split 16 ways in apply
#define APP_CPT (HX_C / APP_SLICES) // 16 channels per thread
#define APP_PIX 16               // float4 pixels per apply block
#define NAPP_BLOCKS (CH_B * HX_HW4 / APP_PIX)   // 512

// scratch (device globals: allocation-free per harness rules)
__device__ float g_avg[HX_B * HX_HW];   // 1 MiB
__device__ float g_max[HX_B * HX_HW];   // 1 MiB

// ---------------------------------------------------------------------------
// Reduce body: mean & max over C=256 for one chunk.
// block = 256 thr = 16 slices x 16 pixels, 16 channels/thread, smem combine.
// ---------------------------------------------------------------------------
__device__ __forceinline__ void reduce_body(const float4* __restrict__ x4,
                                            int b0, int blk) {
    __shared__ float4 s_sum[RED_SLICES * RED_PIX];
    __shared__ float4 s_max[RED_SLICES * RED_PIX];

    int tid   = threadIdx.x;
    int pix   = tid & (RED_PIX - 1);
    int slice = tid >> 4;
    int lpix  = blk * RED_PIX + pix;        // 0..CH_B*HW4-1
    int b     = b0 + (lpix >> 12);          // /4096
    int hw4   = lpix & (HX_HW4 - 1);

    const float4* p = x4 + (size_t)b * HX_C * HX_HW4
                         + (size_t)(slice * RED_CPT) * HX_HW4 + hw4;

    float sx = 0.f, sy = 0.f, sz = 0.f, sw = 0.f;
    float mx = -INFINITY, my = -INFINITY, mz = -INFINITY, mw = -INFINITY;
    #pragma unroll
    for (int c = 0; c < RED_CPT; c++) {
        float4 v = p[(size_t)c * HX_HW4];
        sx += v.x; sy += v.y; sz += v.z; sw += v.w;
        mx = fmaxf(mx, v.x); my = fmaxf(my, v.y);
        mz = fmaxf(mz, v.z); mw = fmaxf(mw, v.w);
    }
    s_sum[tid] = make_float4(sx, sy, sz, sw);
    s_max[tid] = make_float4(mx, my, mz, mw);
    __syncthreads();

    if (slice == 0) {
        float4 a = s_sum[pix];
        float4 m = s_max[pix];
        #pragma unroll
        for (int k = 1; k < RED_SLICES; k++) {
            float4 a2 = s_sum[k * RED_PIX + pix];
            float4 m2 = s_max[k * RED_PIX + pix];
            a.x += a2.x; a.y += a2.y; a.z += a2.z; a.w += a2.w;
            m.x = fmaxf(m.x, m2.x); m.y = fmaxf(m.y, m2.y);
            m.z = fmaxf(m.z, m2.z); m.w = fmaxf(m.w, m2.w);
        }
        const float inv = 1.0f / HX_C;
        a.x *= inv; a.y *= inv; a.z *= inv; a.w *= inv;
        int gpix = b * HX_HW4 + hw4;
        reinterpret_cast<float4*>(g_avg)[gpix] = a;
        reinterpret_cast<float4*>(g_max)[gpix] = m;
    }
}

// ---------------------------------------------------------------------------
// Apply body: per thread, compute sigmoid(stencil) for its 4 pixels once,
// then stream 16 channels: out = x * (1 + sig). x read should hit L2
// (streamed by the reduce of the same chunk one kernel earlier).
// block = 256 thr = 16 slices x 16 pixel-quads.
// ---------------------------------------------------------------------------
__device__ __forceinline__ float ld_plane(const float* __restrict__ y,
                                          int h, int w) {
    return (h >= 0 && h < HX_H && w >= 0 && w < HX_W) ? __ldg(y + h * HX_W + w)
                                                      : 0.f;
}

__device__ __forceinline__ void apply_body(const float4* __restrict__ x4,
                                           float4* __restrict__ o4,
                                           const float* __restrict__ wts,
                                           int b0, int blk) {
    int tid   = threadIdx.x;
    int pix   = tid & (APP_PIX - 1);
    int slice = tid >> 4;
    int lpix  = blk * APP_PIX + pix;        // 0..CH_B*HW4-1
    int b     = b0 + (lpix >> 12);
    int hw4   = lpix & (HX_HW4 - 1);
    int h     = hw4 >> 5;                   // (hw4*4)/128
    int w0    = (hw4 & 31) * 4;

    // stencil + sigmoid for the 4 pixels of this float4
    float acc[4] = {0.f, 0.f, 0.f, 0.f};
    #pragma unroll
    for (int m = 0; m < 2; m++) {
        const float* y = (m == 0 ? g_avg : g_max) + b * HX_HW;
        float p0 = __ldg(wts + b * 8 + m * 4 + 0);
        float p1 = __ldg(wts + b * 8 + m * 4 + 1);
        float p2 = __ldg(wts + b * 8 + m * 4 + 2);
        float p3 = __ldg(wts + b * 8 + m * 4 + 3);
        float pc = -(p0 + p1 + p2 + p3);
        #pragma unroll
        for (int j = 0; j < 4; j++) {
            int w = w0 + j;
            acc[j] += p0 * ld_plane(y, h - 1, w)
                    + p1 * ld_plane(y, h + 1, w)
                    + p2 * ld_plane(y, h, w - 1)
                    + p3 * ld_plane(y, h, w + 1)
                    + pc * ld_plane(y, h, w);
        }
    }
    float f0 = 1.0f + 1.0f / (1.0f + __expf(-acc[0]));
    float f1 = 1.0f + 1.0f / (1.0f + __expf(-acc[1]));
    float f2 = 1.0f + 1.0f / (1.0f + __expf(-acc[2]));
    float f3 = 1.0f + 1.0f / (1.0f + __expf(-acc[3]));

    size_t base = (size_t)b * HX_C * HX_HW4
                + (size_t)(slice * APP_CPT) * HX_HW4 + hw4;
    const float4* px = x4 + base;
    float4*       po = o4 + base;
    #pragma unroll
    for (int c = 0; c < APP_CPT; c++) {
        float4 v = __ldcs(px + (size_t)c * HX_HW4);
        float4 o;
        o.x = v.x * f0; o.y = v.y * f1; o.z = v.z * f2; o.w = v.w * f3;
        __stcs(po + (size_t)c * HX_HW4, o);
    }
}

// ---------------------------------------------------------------------------
// Kernels: prologue reduce, pipelined fused (apply k-1 || reduce k), epilogue.
// ---------------------------------------------------------------------------
__global__ void __launch_bounds__(256) reduce_kernel(const float4* __restrict__ x4,
                                                     int b0) {
    reduce_body(x4, b0, blockIdx.x);
}

__global__ void __launch_bounds__(256) fused_kernel(const float4* __restrict__ x4,
                                                    float4* __restrict__ o4,
                                                    const float* __restrict__ wts,
                                                    int b0_red, int b0_app) {
    if (blockIdx.x < NRED_BLOCKS)
        reduce_body(x4, b0_red, blockIdx.x);
    else
        apply_body(x4, o4, wts, b0_app, blockIdx.x - NRED_BLOCKS);
}

__global__ void __launch_bounds__(256) apply_kernel(const float4* __restrict__ x4,
                                                    float4* __restrict__ o4,
                                                    const float* __restrict__ wts,
                                                    int b0) {
    apply_body(x4, o4, wts, b0, blockIdx.x);
}

extern "C" void kernel_launch(void* const* d_in, const int* in_sizes, int n_in,
                              void* d_out, int out_size) {
    const float4* x4  = (const float4*)d_in[0];
    const float*  wts = (const float*)d_in[1];
    float4*       o4  = (float4*)d_out;

    // prologue: reduce chunk 0
    reduce_kernel<<<NRED_BLOCKS, 256>>>(x4, 0);
    // steady state: apply(k-1) || reduce(k)
    for (int k = 1; k < NCHUNK; k++) {
        fused_kernel<<<NRED_BLOCKS + NAPP_BLOCKS, 256>>>(
            x4, o4, wts, k * CH_B, (k - 1) * CH_B);
    }
    // epilogue: apply last chunk
    apply_kernel<<<NAPP_BLOCKS, 256>>>(x4, o4, wts, (NCHUNK - 1) * CH_B);
}

// round 6
// speedup vs baseline: 1.1294x; 1.1294x over previous
#include <cuda_runtime.h>
#include <math.h>

#define HX_B 16
#define HX_C 256
#define HX_H 128
#define HX_W 128
#define HX_HW (HX_H * HX_W)      // 16384
#define HX_HW4 (HX_HW / 4)       // 4096

#define CH_B 4                   // batches per chunk (64 MiB of x)
#define NCHUNK (HX_B / CH_B)     // 4 chunks

// reduce: block = 16 ch-slices x 16 pixels, 16 channels/thread -> 64 KiB read
#define RED_SLICES 16
#define RED_CPT (HX_C / RED_SLICES)             // 16
#define RED_PIX 16
#define NRED_BLOCKS (CH_B * HX_HW4 / RED_PIX)   // 1024

// apply: block = 32 ch-slices x 8 pixels, 8 channels/thread -> 32K r + 32K w
#define APP_SLICES 32
#define APP_CPT (HX_C / APP_SLICES)             // 8
#define APP_PIX 8
#define NAPP_BLOCKS (CH_B * HX_HW4 / APP_PIX)   // 2048

// scratch (device globals: allocation-free per harness rules)
__device__ float g_avg[HX_B * HX_HW];   // 1 MiB
__device__ float g_max[HX_B * HX_HW];   // 1 MiB

// ---------------------------------------------------------------------------
// Reduce body: mean & max over C=256. Plain loads: x(k) should linger in L2
// for the apply half of the NEXT kernel.
// ---------------------------------------------------------------------------
__device__ __forceinline__ void reduce_body(const float4* __restrict__ x4,
                                            int b0, int blk) {
    __shared__ float4 s_sum[RED_SLICES * RED_PIX];
    __shared__ float4 s_max[RED_SLICES * RED_PIX];

    int tid   = threadIdx.x;
    int pix   = tid & (RED_PIX - 1);
    int slice = tid >> 4;
    int lpix  = blk * RED_PIX + pix;        // 0..CH_B*HW4-1
    int b     = b0 + (lpix >> 12);          // /4096
    int hw4   = lpix & (HX_HW4 - 1);

    const float4* p = x4 + (size_t)b * HX_C * HX_HW4
                         + (size_t)(slice * RED_CPT) * HX_HW4 + hw4;

    float sx = 0.f, sy = 0.f, sz = 0.f, sw = 0.f;
    float mx = -INFINITY, my = -INFINITY, mz = -INFINITY, mw = -INFINITY;
    #pragma unroll
    for (int c = 0; c < RED_CPT; c++) {
        float4 v = p[(size_t)c * HX_HW4];
        sx += v.x; sy += v.y; sz += v.z; sw += v.w;
        mx = fmaxf(mx, v.x); my = fmaxf(my, v.y);
        mz = fmaxf(mz, v.z); mw = fmaxf(mw, v.w);
    }
    s_sum[tid] = make_float4(sx, sy, sz, sw);
    s_max[tid] = make_float4(mx, my, mz, mw);
    __syncthreads();

    if (slice == 0) {
        float4 a = s_sum[pix];
        float4 m = s_max[pix];
        #pragma unroll
        for (int k = 1; k < RED_SLICES; k++) {
            float4 a2 = s_sum[k * RED_PIX + pix];
            float4 m2 = s_max[k * RED_PIX + pix];
            a.x += a2.x; a.y += a2.y; a.z += a2.z; a.w += a2.w;
            m.x = fmaxf(m.x, m2.x); m.y = fmaxf(m.y, m2.y);
            m.z = fmaxf(m.z, m2.z); m.w = fmaxf(m.w, m2.w);
        }
        const float inv = 1.0f / HX_C;
        a.x *= inv; a.y *= inv; a.z *= inv; a.w *= inv;
        int gpix = b * HX_HW4 + hw4;
        reinterpret_cast<float4*>(g_avg)[gpix] = a;
        reinterpret_cast<float4*>(g_max)[gpix] = m;
    }
}

// ---------------------------------------------------------------------------
// Apply body: slice-0 threads compute sigmoid(stencil) once per pixel into
// smem; then all 256 threads stream 8 channels each:
// out = x * (1 + sig). x reads via __ldcs (dead after), stores __stcs.
// ---------------------------------------------------------------------------
__device__ __forceinline__ float ld_plane(const float* __restrict__ y,
                                          int h, int w) {
    return (h >= 0 && h < HX_H && w >= 0 && w < HX_W) ? __ldg(y + h * HX_W + w)
                                                      : 0.f;
}

__device__ __forceinline__ void apply_body(const float4* __restrict__ x4,
                                           float4* __restrict__ o4,
                                           const float* __restrict__ wts,
                                           int b0, int blk) {
    __shared__ float4 s_f[APP_PIX];         // per-pixel-quad (1+sig) factors

    int tid   = threadIdx.x;
    int pix   = tid & (APP_PIX - 1);
    int slice = tid >> 3;                   // 0..31
    int lpix  = blk * APP_PIX + pix;        // 0..CH_B*HW4-1
    int b     = b0 + (lpix >> 12);
    int hw4   = lpix & (HX_HW4 - 1);

    if (slice == 0) {
        int h  = hw4 >> 5;                  // (hw4*4)/128
        int w0 = (hw4 & 31) * 4;
        float acc[4] = {0.f, 0.f, 0.f, 0.f};
        #pragma unroll
        for (int m = 0; m < 2; m++) {
            const float* y = (m == 0 ? g_avg : g_max) + b * HX_HW;
            float p0 = __ldg(wts + b * 8 + m * 4 + 0);
            float p1 = __ldg(wts + b * 8 + m * 4 + 1);
            float p2 = __ldg(wts + b * 8 + m * 4 + 2);
            float p3 = __ldg(wts + b * 8 + m * 4 + 3);
            float pc = -(p0 + p1 + p2 + p3);
            #pragma unroll
            for (int j = 0; j < 4; j++) {
                int w = w0 + j;
                acc[j] += p0 * ld_plane(y, h - 1, w)
                        + p1 * ld_plane(y, h + 1, w)
                        + p2 * ld_plane(y, h, w - 1)
                        + p3 * ld_plane(y, h, w + 1)
                        + pc * ld_plane(y, h, w);
            }
        }
        s_f[pix] = make_float4(1.0f + 1.0f / (1.0f + __expf(-acc[0])),
                               1.0f + 1.0f / (1.0f + __expf(-acc[1])),
                               1.0f + 1.0f / (1.0f + __expf(-acc[2])),
                               1.0f + 1.0f / (1.0f + __expf(-acc[3])));
    }
    __syncthreads();
    float4 f = s_f[pix];

    size_t base = (size_t)b * HX_C * HX_HW4
                + (size_t)(slice * APP_CPT) * HX_HW4 + hw4;
    const float4* px = x4 + base;
    float4*       po = o4 + base;
    #pragma unroll
    for (int c = 0; c < APP_CPT; c++) {
        float4 v = __ldcs(px + (size_t)c * HX_HW4);
        float4 o;
        o.x = v.x * f.x; o.y = v.y * f.y; o.z = v.z * f.z; o.w = v.w * f.w;
        __stcs(po + (size_t)c * HX_HW4, o);
    }
}

// ---------------------------------------------------------------------------
// Kernels. Fused grid interleaves 1 reduce block per 2 apply blocks so DRAM
// reads (reduce) and writes (apply) stay concurrently in flight.
// ---------------------------------------------------------------------------
__global__ void __launch_bounds__(256) reduce_kernel(const float4* __restrict__ x4,
                                                     int b0) {
    reduce_body(x4, b0, blockIdx.x);
}

__global__ void __launch_bounds__(256) fused_kernel(const float4* __restrict__ x4,
                                                    float4* __restrict__ o4,
                                                    const float* __restrict__ wts,
                                                    int b0_red, int b0_app) {
    int grp  = blockIdx.x / 3;
    int lane = blockIdx.x - grp * 3;
    if (lane == 0)
        reduce_body(x4, b0_red, grp);               // 1024 reduce blocks
    else
        apply_body(x4, o4, wts, b0_app, grp * 2 + (lane - 1)); // 2048 apply
}

__global__ void __launch_bounds__(256) apply_kernel(const float4* __restrict__ x4,
                                                    float4* __restrict__ o4,
                                                    const float* __restrict__ wts,
                                                    int b0) {
    apply_body(x4, o4, wts, b0, blockIdx.x);
}

extern "C" void kernel_launch(void* const* d_in, const int* in_sizes, int n_in,
                              void* d_out, int out_size) {
    const float4* x4  = (const float4*)d_in[0];
    const float*  wts = (const float*)d_in[1];
    float4*       o4  = (float4*)d_out;

    // prologue: reduce chunk 0
    reduce_kernel<<<NRED_BLOCKS, 256>>>(x4, 0);
    // steady state: reduce(k) interleaved with apply(k-1)
    for (int k = 1; k < NCHUNK; k++) {
        fused_kernel<<<NRED_BLOCKS + NAPP_BLOCKS, 256>>>(
            x4, o4, wts, k * CH_B, (k - 1) * CH_B);
    }
    // epilogue: apply last chunk
    apply_kernel<<<NAPP_BLOCKS, 256>>>(x4, o4, wts, (NCHUNK - 1) * CH_B);
}

// round 9
// speedup vs baseline: 1.1410x; 1.0103x over previous
#include <cuda_runtime.h>
#include <math.h>

#define HX_B 16
#define HX_C 256
#define HX_H 128
#define HX_W 128
#define HX_HW (HX_H * HX_W)      // 16384
#define HX_HW4 (HX_HW / 4)       // 4096

#define CH_B 2                   // batches per chunk (32 MiB of x)
#define NCHUNK (HX_B / CH_B)     // 8 chunks

#define PIXQ 8                   // float4 pixel-quads per unit
#define SLICES 32                // channel slices per unit
#define CPT (HX_C / SLICES)      // 8 channels per thread
#define NBLK (CH_B * HX_HW4 / PIXQ)   // 1024 blocks per step

// scratch (device globals: allocation-free per harness rules)
__device__ float g_avg[HX_B * HX_HW];   // 1 MiB
__device__ float g_max[HX_B * HX_HW];   // 1 MiB

// ---------------------------------------------------------------------------
// Reduce unit: 8 pixel-quads, full C. thread = slice*8+pix, 8 ch/thread.
// 32 KiB DRAM read per block. Default cache policy: x(k) must linger in L2
// for the next step's apply part.
// ---------------------------------------------------------------------------
__device__ __forceinline__ void reduce_body(const float4* __restrict__ x4,
                                            int b0, int blk) {
    __shared__ float4 s_sum[SLICES * PIXQ];
    __shared__ float4 s_max[SLICES * PIXQ];

    int tid   = threadIdx.x;
    int pix   = tid & (PIXQ - 1);
    int slice = tid >> 3;
    int lpix  = blk * PIXQ + pix;           // 0..CH_B*HW4-1
    int b     = b0 + (lpix >> 12);          // /4096
    int hw4   = lpix & (HX_HW4 - 1);

    const float4* p = x4 + (size_t)b * HX_C * HX_HW4
                         + (size_t)(slice * CPT) * HX_HW4 + hw4;

    float sx = 0.f, sy = 0.f, sz = 0.f, sw = 0.f;
    float mx = -INFINITY, my = -INFINITY, mz = -INFINITY, mw = -INFINITY;
    #pragma unroll
    for (int c = 0; c < CPT; c++) {
        float4 v = p[(size_t)c * HX_HW4];
        sx += v.x; sy += v.y; sz += v.z; sw += v.w;
        mx = fmaxf(mx, v.x); my = fmaxf(my, v.y);
        mz = fmaxf(mz, v.z); mw = fmaxf(mw, v.w);
    }
    s_sum[tid] = make_float4(sx, sy, sz, sw);
    s_max[tid] = make_float4(mx, my, mz, mw);
    __syncthreads();

    if (tid < PIXQ) {                       // 8 threads: sums
        float4 a = s_sum[tid];
        #pragma unroll
        for (int k = 1; k < SLICES; k++) {
            float4 a2 = s_sum[k * PIXQ + tid];
            a.x += a2.x; a.y += a2.y; a.z += a2.z; a.w += a2.w;
        }
        const float inv = 1.0f / HX_C;
        a.x *= inv; a.y *= inv; a.z *= inv; a.w *= inv;
        int gp = (b0 + ((blk * PIXQ + tid) >> 12)) * HX_HW4
               + ((blk * PIXQ + tid) & (HX_HW4 - 1));
        reinterpret_cast<float4*>(g_avg)[gp] = a;
    } else if (tid < 2 * PIXQ) {            // 8 threads: maxes
        int q = tid - PIXQ;
        float4 m = s_max[q];
        #pragma unroll
        for (int k = 1; k < SLICES; k++) {
            float4 m2 = s_max[k * PIXQ + q];
            m.x = fmaxf(m.x, m2.x); m.y = fmaxf(m.y, m2.y);
            m.z = fmaxf(m.z, m2.z); m.w = fmaxf(m.w, m2.w);
        }
        int gp = (b0 + ((blk * PIXQ + q) >> 12)) * HX_HW4
               + ((blk * PIXQ + q) & (HX_HW4 - 1));
        reinterpret_cast<float4*>(g_max)[gp] = m;
    }
}

// ---------------------------------------------------------------------------
// Apply unit: 8 pixel-quads, full C. One warp computes the 32 sub-pixel
// stencil+sigmoid factors into smem; then all 256 threads stream 8 ch each:
// out = x * (1 + sig). __ldcs/__stcs: dead-after-use, evict-first.
// ---------------------------------------------------------------------------
__device__ __forceinline__ float ld_plane(const float* __restrict__ y,
                                          int h, int w) {
    return (h >= 0 && h < HX_H && w >= 0 && w < HX_W) ? __ldg(y + h * HX_W + w)
                                                      : 0.f;
}

__device__ __forceinline__ void apply_body(const float4* __restrict__ x4,
                                           float4* __restrict__ o4,
                                           const float* __restrict__ wts,
                                           int b0, int blk) {
    __shared__ __align__(16) float s_fac[PIXQ * 4];   // 32 sub-pixel factors

    int tid   = threadIdx.x;
    int pix   = tid & (PIXQ - 1);
    int slice = tid >> 3;
    int lpix  = blk * PIXQ + pix;
    int b     = b0 + (lpix >> 12);
    int hw4   = lpix & (HX_HW4 - 1);

    if (tid < 32) {                         // warp 0: one sub-pixel per lane
        int q   = tid >> 2;                 // quad 0..7
        int sub = tid & 3;
        int lq  = blk * PIXQ + q;
        int bq  = b0 + (lq >> 12);
        int hq4 = lq & (HX_HW4 - 1);
        int h   = hq4 >> 5;
        int w   = (hq4 & 31) * 4 + sub;
        float acc = 0.f;
        #pragma unroll
        for (int m = 0; m < 2; m++) {
            const float* y = (m == 0 ? g_avg : g_max) + bq * HX_HW;
            float p0 = __ldg(wts + bq * 8 + m * 4 + 0);
            float p1 = __ldg(wts + bq * 8 + m * 4 + 1);
            float p2 = __ldg(wts + bq * 8 + m * 4 + 2);
            float p3 = __ldg(wts + bq * 8 + m * 4 + 3);
            float pc = -(p0 + p1 + p2 + p3);
            acc += p0 * ld_plane(y, h - 1, w)
                 + p1 * ld_plane(y, h + 1, w)
                 + p2 * ld_plane(y, h, w - 1)
                 + p3 * ld_plane(y, h, w + 1)
                 + pc * ld_plane(y, h, w);
        }
        s_fac[tid] = 1.0f + 1.0f / (1.0f + __expf(-acc));
    }
    __syncthreads();
    float4 f = reinterpret_cast<const float4*>(s_fac)[pix];

    size_t base = (size_t)b * HX_C * HX_HW4
                + (size_t)(slice * CPT) * HX_HW4 + hw4;
    const float4* px = x4 + base;
    float4*       po = o4 + base;
    #pragma unroll
    for (int c = 0; c < CPT; c++) {
        float4 v = __ldcs(px + (size_t)c * HX_HW4);
        float4 o;
        o.x = v.x * f.x; o.y = v.y * f.y; o.z = v.z * f.z; o.w = v.w * f.w;
        __stcs(po + (size_t)c * HX_HW4, o);
    }
}

// ---------------------------------------------------------------------------
// Kernels: uniform fused blocks — apply(k-1) first (L2-hot), reduce(k) second.
// ---------------------------------------------------------------------------
__global__ void __launch_bounds__(256) reduce_kernel(const float4* __restrict__ x4,
                                                     int b0) {
    reduce_body(x4, b0, blockIdx.x);
}

__global__ void __launch_bounds__(256) fused_kernel(const float4* __restrict__ x4,
                                                    float4* __restrict__ o4,
                                                    const float* __restrict__ wts,
                                                    int b0_red, int b0_app) {
    apply_body(x4, o4, wts, b0_app, blockIdx.x);
    __syncthreads();
    reduce_body(x4, b0_red, blockIdx.x);
}

__global__ void __launch_bounds__(256) apply_kernel(const float4* __restrict__ x4,
                                                    float4* __restrict__ o4,
                                                    const float* __restrict__ wts,
                                                    int b0) {
    apply_body(x4, o4, wts, b0, blockIdx.x);
}

extern "C" void kernel_launch(void* const* d_in, const int* in_sizes, int n_in,
                              void* d_out, int out_size) {
    const float4* x4  = (const float4*)d_in[0];
    const float*  wts = (const float*)d_in[1];
    float4*       o4  = (float4*)d_out;

    // prologue: reduce chunk 0
    reduce_kernel<<<NBLK, 256>>>(x4, 0);
    // steady state: uniform blocks, apply(k-1) then reduce(k)
    for (int k = 1; k < NCHUNK; k++) {
        fused_kernel<<<NBLK, 256>>>(x4, o4, wts, k * CH_B, (k - 1) * CH_B);
    }
    // epilogue: apply last chunk
    apply_kernel<<<NBLK, 256>>>(x4, o4, wts, (NCHUNK - 1) * CH_B);
}

// round 10
// speedup vs baseline: 1.3266x; 1.1627x over previous
#include <cuda_runtime.h>
#include <math.h>

#define HX_B 16
#define HX_C 256
#define HX_H 128
#define HX_W 128
#define HX_HW (HX_H * HX_W)      // 16384
#define HX_HW4 (HX_HW / 4)       // 4096

#define CH_B 4                   // batches per chunk (64 MiB of x)
#define NCHUNK (HX_B / CH_B)     // 4 chunks

// reduce: block = 16 ch-slices x 16 pixel-quads, 16 channels/thread
#define RED_SLICES 16
#define RED_CPT (HX_C / RED_SLICES)             // 16
#define RED_PIX 16
#define NRED_BLOCKS (CH_B * HX_HW4 / RED_PIX)   // 1024

// apply: block = 32 ch-slices x 8 pixel-quads, 8 channels/thread
#define APP_SLICES 32
#define APP_CPT (HX_C / APP_SLICES)             // 8
#define APP_PIX 8
#define NAPP_BLOCKS (CH_B * HX_HW4 / APP_PIX)   // 2048

// scratch (device globals: allocation-free per harness rules)
__device__ float g_avg[HX_B * HX_HW];   // 1 MiB
__device__ float g_max[HX_B * HX_HW];   // 1 MiB

// ---------------------------------------------------------------------------
// Reduce (per chunk): mean & max over C=256. Default cache policy — x(k)
// must linger in L2 for the immediately-following apply(k).
// __launch_bounds__(256, 8): cap regs at 32 so 8 blocks/SM (occ ~100%).
// ---------------------------------------------------------------------------
__global__ void __launch_bounds__(256, 8) reduce_kernel(const float4* __restrict__ x4,
                                                        int b0) {
    __shared__ float4 s_sum[RED_SLICES * RED_PIX];
    __shared__ float4 s_max[RED_SLICES * RED_PIX];

    int tid   = threadIdx.x;
    int pix   = tid & (RED_PIX - 1);        // 0..15
    int slice = tid >> 4;                   // 0..15
    int lpix  = blockIdx.x * RED_PIX + pix; // 0..CH_B*HW4-1
    int b     = b0 + (lpix >> 12);          // /4096
    int hw4   = lpix & (HX_HW4 - 1);

    const float4* p = x4 + (size_t)b * HX_C * HX_HW4
                         + (size_t)(slice * RED_CPT) * HX_HW4 + hw4;

    float sx = 0.f, sy = 0.f, sz = 0.f, sw = 0.f;
    float mx = -INFINITY, my = -INFINITY, mz = -INFINITY, mw = -INFINITY;
    #pragma unroll
    for (int c = 0; c < RED_CPT; c++) {
        float4 v = p[(size_t)c * HX_HW4];
        sx += v.x; sy += v.y; sz += v.z; sw += v.w;
        mx = fmaxf(mx, v.x); my = fmaxf(my, v.y);
        mz = fmaxf(mz, v.z); mw = fmaxf(mw, v.w);
    }
    s_sum[tid] = make_float4(sx, sy, sz, sw);
    s_max[tid] = make_float4(mx, my, mz, mw);
    __syncthreads();

    // 16 threads combine sums, 16 combine maxes (parallel, fewer idle lanes)
    if (tid < RED_PIX) {
        float4 a = s_sum[tid];
        #pragma unroll
        for (int k = 1; k < RED_SLICES; k++) {
            float4 a2 = s_sum[k * RED_PIX + tid];
            a.x += a2.x; a.y += a2.y; a.z += a2.z; a.w += a2.w;
        }
        const float inv = 1.0f / HX_C;
        a.x *= inv; a.y *= inv; a.z *= inv; a.w *= inv;
        int lp = blockIdx.x * RED_PIX + tid;
        int gp = (b0 + (lp >> 12)) * HX_HW4 + (lp & (HX_HW4 - 1));
        reinterpret_cast<float4*>(g_avg)[gp] = a;
    } else if (tid < 2 * RED_PIX) {
        int q = tid - RED_PIX;
        float4 m = s_max[q];
        #pragma unroll
        for (int k = 1; k < RED_SLICES; k++) {
            float4 m2 = s_max[k * RED_PIX + q];
            m.x = fmaxf(m.x, m2.x); m.y = fmaxf(m.y, m2.y);
            m.z = fmaxf(m.z, m2.z); m.w = fmaxf(m.w, m2.w);
        }
        int lp = blockIdx.x * RED_PIX + q;
        int gp = (b0 + (lp >> 12)) * HX_HW4 + (lp & (HX_HW4 - 1));
        reinterpret_cast<float4*>(g_max)[gp] = m;
    }
}

// ---------------------------------------------------------------------------
// Apply (per chunk): warp 0 computes the 32 sub-pixel stencil+sigmoid
// factors into smem; then all 256 threads stream 8 channels each:
// out = x * (1 + sig). x reads __ldcs (L2-hot from reduce, dead after),
// stores __stcs (evict-first: don't displace next chunk's x).
// ---------------------------------------------------------------------------
__device__ __forceinline__ float ld_plane(const float* __restrict__ y,
                                          int h, int w) {
    return (h >= 0 && h < HX_H && w >= 0 && w < HX_W) ? __ldg(y + h * HX_W + w)
                                                      : 0.f;
}

__global__ void __launch_bounds__(256, 8) apply_kernel(const float4* __restrict__ x4,
                                                       float4* __restrict__ o4,
                                                       const float* __restrict__ wts,
                                                       int b0) {
    __shared__ __align__(16) float s_fac[APP_PIX * 4];   // 32 sub-pixel factors

    int tid   = threadIdx.x;
    int pix   = tid & (APP_PIX - 1);        // 0..7
    int slice = tid >> 3;                   // 0..31
    int lpix  = blockIdx.x * APP_PIX + pix;
    int b     = b0 + (lpix >> 12);
    int hw4   = lpix & (HX_HW4 - 1);

    if (tid < 32) {                         // warp 0: one sub-pixel per lane
        int q   = tid >> 2;                 // quad 0..7
        int sub = tid & 3;
        int lq  = blockIdx.x * APP_PIX + q;
        int bq  = b0 + (lq >> 12);
        int hq4 = lq & (HX_HW4 - 1);
        int h   = hq4 >> 5;
        int w   = (hq4 & 31) * 4 + sub;
        float acc = 0.f;
        #pragma unroll
        for (int m = 0; m < 2; m++) {
            const float* y = (m == 0 ? g_avg : g_max) + bq * HX_HW;
            float p0 = __ldg(wts + bq * 8 + m * 4 + 0);
            float p1 = __ldg(wts + bq * 8 + m * 4 + 1);
            float p2 = __ldg(wts + bq * 8 + m * 4 + 2);
            float p3 = __ldg(wts + bq * 8 + m * 4 + 3);
            float pc = -(p0 + p1 + p2 + p3);
            acc += p0 * ld_plane(y, h - 1, w)
                 + p1 * ld_plane(y, h + 1, w)
                 + p2 * ld_plane(y, h, w - 1)
                 + p3 * ld_plane(y, h, w + 1)
                 + pc * ld_plane(y, h, w);
        }
        s_fac[tid] = 1.0f + 1.0f / (1.0f + __expf(-acc));
    }
    __syncthreads();
    float4 f = reinterpret_cast<const float4*>(s_fac)[pix];

    size_t base = (size_t)b * HX_C * HX_HW4
                + (size_t)(slice * APP_CPT) * HX_HW4 + hw4;
    const float4* px = x4 + base;
    float4*       po = o4 + base;
    #pragma unroll
    for (int c = 0; c < APP_CPT; c++) {
        float4 v = __ldcs(px + (size_t)c * HX_HW4);
        float4 o;
        o.x = v.x * f.x; o.y = v.y * f.y; o.z = v.z * f.z; o.w = v.w * f.w;
        __stcs(po + (size_t)c * HX_HW4, o);
    }
}

extern "C" void kernel_launch(void* const* d_in, const int* in_sizes, int n_in,
                              void* d_out, int out_size) {
    const float4* x4  = (const float4*)d_in[0];
    const float*  wts = (const float*)d_in[1];
    float4*       o4  = (float4*)d_out;

    for (int k = 0; k < NCHUNK; k++) {
        int b0 = k * CH_B;
        reduce_kernel<<<NRED_BLOCKS, 256>>>(x4, b0);
        apply_kernel<<<NAPP_BLOCKS, 256>>>(x4, o4, wts, b0);
    }
}

// round 13
// speedup vs baseline: 1.3789x; 1.0394x over previous
#include <cuda_runtime.h>
#include <math.h>

#define HX_B 16
#define HX_C 256
#define HX_H 128
#define HX_W 128
#define HX_HW (HX_H * HX_W)      // 16384
#define HX_HW4 (HX_HW / 4)       // 4096

#define CH_B 4                   // batches per chunk (64 MiB of x)
#define NCHUNK (HX_B / CH_B)     // 4 chunks

// reduce: block = 16 ch-slices x 16 pixel-quads, 16 channels/thread
#define RED_SLICES 16
#define RED_CPT (HX_C / RED_SLICES)             // 16
#define RED_PIX 16
#define NRED_BLOCKS (CH_B * HX_HW4 / RED_PIX)   // 1024

// apply: block = 32 ch-slices x 8 pixel-quads, 8 channels/thread
#define APP_SLICES 32
#define APP_CPT (HX_C / APP_SLICES)             // 8
#define APP_PIX 8
#define NAPP_BLOCKS (CH_B * HX_HW4 / APP_PIX)   // 2048

// scratch (device globals: allocation-free per harness rules)
__device__ float g_avg[HX_B * HX_HW];   // 1 MiB
__device__ float g_max[HX_B * HX_HW];   // 1 MiB

// ---------------------------------------------------------------------------
// Reduce (per chunk): mean & max over C=256. Default cache policy — x(k)
// must linger in L2 for the immediately-following apply(k).
// UNCHANGED from round 10: runs at ~7.3 TB/s, at the ceiling.
// ---------------------------------------------------------------------------
__global__ void __launch_bounds__(256, 8) reduce_kernel(const float4* __restrict__ x4,
                                                        int b0) {
    __shared__ float4 s_sum[RED_SLICES * RED_PIX];
    __shared__ float4 s_max[RED_SLICES * RED_PIX];

    int tid   = threadIdx.x;
    int pix   = tid & (RED_PIX - 1);        // 0..15
    int slice = tid >> 4;                   // 0..15
    int lpix  = blockIdx.x * RED_PIX + pix; // 0..CH_B*HW4-1
    int b     = b0 + (lpix >> 12);          // /4096
    int hw4   = lpix & (HX_HW4 - 1);

    const float4* p = x4 + (size_t)b * HX_C * HX_HW4
                         + (size_t)(slice * RED_CPT) * HX_HW4 + hw4;

    float sx = 0.f, sy = 0.f, sz = 0.f, sw = 0.f;
    float mx = -INFINITY, my = -INFINITY, mz = -INFINITY, mw = -INFINITY;
    #pragma unroll
    for (int c = 0; c < RED_CPT; c++) {
        float4 v = p[(size_t)c * HX_HW4];
        sx += v.x; sy += v.y; sz += v.z; sw += v.w;
        mx = fmaxf(mx, v.x); my = fmaxf(my, v.y);
        mz = fmaxf(mz, v.z); mw = fmaxf(mw, v.w);
    }
    s_sum[tid] = make_float4(sx, sy, sz, sw);
    s_max[tid] = make_float4(mx, my, mz, mw);
    __syncthreads();

    if (tid < RED_PIX) {
        float4 a = s_sum[tid];
        #pragma unroll
        for (int k = 1; k < RED_SLICES; k++) {
            float4 a2 = s_sum[k * RED_PIX + tid];
            a.x += a2.x; a.y += a2.y; a.z += a2.z; a.w += a2.w;
        }
        const float inv = 1.0f / HX_C;
        a.x *= inv; a.y *= inv; a.z *= inv; a.w *= inv;
        int lp = blockIdx.x * RED_PIX + tid;
        int gp = (b0 + (lp >> 12)) * HX_HW4 + (lp & (HX_HW4 - 1));
        reinterpret_cast<float4*>(g_avg)[gp] = a;
    } else if (tid < 2 * RED_PIX) {
        int q = tid - RED_PIX;
        float4 m = s_max[q];
        #pragma unroll
        for (int k = 1; k < RED_SLICES; k++) {
            float4 m2 = s_max[k * RED_PIX + q];
            m.x = fmaxf(m.x, m2.x); m.y = fmaxf(m.y, m2.y);
            m.z = fmaxf(m.z, m2.z); m.w = fmaxf(m.w, m2.w);
        }
        int lp = blockIdx.x * RED_PIX + q;
        int gp = (b0 + (lp >> 12)) * HX_HW4 + (lp & (HX_HW4 - 1));
        reinterpret_cast<float4*>(g_max)[gp] = m;
    }
}

// ---------------------------------------------------------------------------
// Apply (per chunk): warp 0 computes the 32 sub-pixel stencil+sigmoid
// factors; then all 256 threads stream 8 channels each as TWO BATCHES of
// 4 front-loaded float4s (MLP=4) -> scale -> store.
// launch_bounds(256,6): allow ~42 regs so 4 loads stay in flight.
// ---------------------------------------------------------------------------
__device__ __forceinline__ float ld_plane(const float* __restrict__ y,
                                          int h, int w) {
    return (h >= 0 && h < HX_H && w >= 0 && w < HX_W) ? __ldg(y + h * HX_W + w)
                                                      : 0.f;
}

__global__ void __launch_bounds__(256, 6) apply_kernel(const float4* __restrict__ x4,
                                                       float4* __restrict__ o4,
                                                       const float* __restrict__ wts,
                                                       int b0) {
    __shared__ __align__(16) float s_fac[APP_PIX * 4];   // 32 sub-pixel factors

    int tid   = threadIdx.x;
    int pix   = tid & (APP_PIX - 1);        // 0..7
    int slice = tid >> 3;                   // 0..31
    int lpix  = blockIdx.x * APP_PIX + pix;
    int b     = b0 + (lpix >> 12);
    int hw4   = lpix & (HX_HW4 - 1);

    if (tid < 32) {                         // warp 0: one sub-pixel per lane
        int q   = tid >> 2;                 // quad 0..7
        int sub = tid & 3;
        int lq  = blockIdx.x * APP_PIX + q;
        int bq  = b0 + (lq >> 12);
        int hq4 = lq & (HX_HW4 - 1);
        int h   = hq4 >> 5;
        int w   = (hq4 & 31) * 4 + sub;
        float acc = 0.f;
        #pragma unroll
        for (int m = 0; m < 2; m++) {
            const float* y = (m == 0 ? g_avg : g_max) + bq * HX_HW;
            float p0 = __ldg(wts + bq * 8 + m * 4 + 0);
            float p1 = __ldg(wts + bq * 8 + m * 4 + 1);
            float p2 = __ldg(wts + bq * 8 + m * 4 + 2);
            float p3 = __ldg(wts + bq * 8 + m * 4 + 3);
            float pc = -(p0 + p1 + p2 + p3);
            acc += p0 * ld_plane(y, h - 1, w)
                 + p1 * ld_plane(y, h + 1, w)
                 + p2 * ld_plane(y, h, w - 1)
                 + p3 * ld_plane(y, h, w + 1)
                 + pc * ld_plane(y, h, w);
        }
        s_fac[tid] = 1.0f + 1.0f / (1.0f + __expf(-acc));
    }
    __syncthreads();
    float4 f = reinterpret_cast<const float4*>(s_fac)[pix];

    size_t base = (size_t)b * HX_C * HX_HW4
                + (size_t)(slice * APP_CPT) * HX_HW4 + hw4;
    const float4* px = x4 + base;
    float4*       po = o4 + base;

    #pragma unroll
    for (int batch = 0; batch < APP_CPT / 4; batch++) {
        float4 v0 = __ldcs(px + (size_t)(batch * 4 + 0) * HX_HW4);
        float4 v1 = __ldcs(px + (size_t)(batch * 4 + 1) * HX_HW4);
        float4 v2 = __ldcs(px + (size_t)(batch * 4 + 2) * HX_HW4);
        float4 v3 = __ldcs(px + (size_t)(batch * 4 + 3) * HX_HW4);
        v0.x *= f.x; v0.y *= f.y; v0.z *= f.z; v0.w *= f.w;
        v1.x *= f.x; v1.y *= f.y; v1.z *= f.z; v1.w *= f.w;
        v2.x *= f.x; v2.y *= f.y; v2.z *= f.z; v2.w *= f.w;
        v3.x *= f.x; v3.y *= f.y; v3.z *= f.z; v3.w *= f.w;
        __stcs(po + (size_t)(batch * 4 + 0) * HX_HW4, v0);
        __stcs(po + (size_t)(batch * 4 + 1) * HX_HW4, v1);
        __stcs(po + (size_t)(batch * 4 + 2) * HX_HW4, v2);
        __stcs(po + (size_t)(batch * 4 + 3) * HX_HW4, v3);
    }
}

extern "C" void kernel_launch(void* const* d_in, const int* in_sizes, int n_in,
                              void* d_out, int out_size) {
    const float4* x4  = (const float4*)d_in[0];
    const float*  wts = (const float*)d_in[1];
    float4*       o4  = (float4*)d_out;

    for (int k = 0; k < NCHUNK; k++) {
        int b0 = k * CH_B;
        reduce_kernel<<<NRED_BLOCKS, 256>>>(x4, b0);
        apply_kernel<<<NAPP_BLOCKS, 256>>>(x4, o4, wts, b0);
    }
}